// round 14
// baseline (speedup 1.0000x reference)
#include <cuda_runtime.h>
#include <cuda_bf16.h>
#include <cstdint>

#define B_ 4
#define CX 512
#define CY 256
#define M_ 64
#define N_ 4096
#define EPS_ 1e-5f
#define INVT_ (1.0f / 16384.0f)

typedef unsigned long long u64;

__device__ __forceinline__ u64 d2(float v){u64 r;asm("mov.b64 %0,{%1,%1};":"=l"(r):"f"(v));return r;}
__device__ __forceinline__ void up2(u64 v,float&a,float&b){asm("mov.b64 {%0,%1},%2;":"=f"(a),"=f"(b):"l"(v));}
__device__ __forceinline__ void fma2(u64&d,u64 a,u64 b){asm("fma.rn.f32x2 %0,%1,%2,%0;":"+l"(d):"l"(a),"l"(b));}
__device__ __forceinline__ uint32_t pkbf(float lo,float hi){uint32_t r;asm("cvt.rn.bf16x2.f32 %0, %1, %2;":"=r"(r):"f"(hi),"f"(lo));return r;}
__device__ __forceinline__ float bflo(uint32_t p){return __uint_as_float(p<<16);}
__device__ __forceinline__ float bfhi(uint32_t p){return __uint_as_float(p&0xffff0000u);}
__device__ __forceinline__ uint32_t s2u(const void*p){uint32_t a;asm("{ .reg .u64 t; cvta.to.shared.u64 t, %1; cvt.u32.u64 %0, t; }":"=r"(a):"l"(p));return a;}

__device__ __forceinline__ void ldsm4(uint32_t a, uint32_t* r){
    asm volatile("ldmatrix.sync.aligned.m8n8.x4.shared.b16 {%0,%1,%2,%3}, [%4];"
        :"=r"(r[0]),"=r"(r[1]),"=r"(r[2]),"=r"(r[3]):"r"(a));
}
__device__ __forceinline__ void mma16816(float* c, const uint32_t* a, uint32_t b0, uint32_t b1){
    asm volatile("mma.sync.aligned.m16n8k16.row.col.f32.bf16.bf16.f32 {%0,%1,%2,%3},{%4,%5,%6,%7},{%8,%9},{%0,%1,%2,%3};"
        :"+f"(c[0]),"+f"(c[1]),"+f"(c[2]),"+f"(c[3])
        :"r"(a[0]),"r"(a[1]),"r"(a[2]),"r"(a[3]),"r"(b0),"r"(b1));
}
__device__ __forceinline__ uint32_t fraddr(uint32_t base, int r0, int k0, int stride, int lane){
    int row = r0 + (lane&7) + ((lane&8)?8:0);
    int col = k0 + ((lane&16)?8:0);
    return base + row*stride + col*2;
}

__device__ __align__(16) float g_z1[3*B_*M_*N_];
__device__ __align__(16) float g_fout[B_*M_*N_];
__device__ __align__(16) unsigned int g_qh[B_*N_*32], g_ql[B_*N_*32];   // [b][n][64m] bf16
__device__ __align__(16) unsigned int g_kh[B_*N_*32], g_kl[B_*N_*32];   // [b][n][64m] bf16
__device__ __align__(16) unsigned int g_vh[B_*M_*N_/2], g_vl[B_*M_*N_/2]; // [b][c][n] bf16
__device__ float g_gram1[3*64*64];
__device__ float g_sum1[192];
__device__ unsigned int g_cnt1;
__device__ __align__(16) float g_w2eff[3*64*64];
__device__ float g_beff[192];
__device__ float g_gramf[64*64];
__device__ float g_sumf[64];
__device__ float g_au[512], g_bu[512];

__global__ __launch_bounds__(256) void k_gemm1(
    const float* __restrict__ x, const float* __restrict__ y,
    const float* __restrict__ ws1, const float* __restrict__ wx1, const float* __restrict__ wy1)
{
    __shared__ __align__(16) float Ws[16*68];
    __shared__ __align__(16) float Xs[16*132];
    int p=blockIdx.z, b=blockIdx.y, n0=blockIdx.x*128;
    const float* W=(p==0)?ws1:(p==1)?wx1:wy1;
    const float* X=(p==2)?(y+(size_t)b*CY*N_):(x+(size_t)b*CX*N_);
    int K=(p==2)?CY:CX;
    float* C=g_z1+((size_t)(p*B_+b)*M_)*N_+n0;
    int tid=threadIdx.x, ty=tid>>5, tx=tid&31;
    u64 acc[4][4];
#pragma unroll
    for(int r=0;r<4;++r){acc[r][0]=acc[r][1]=acc[r][2]=acc[r][3]=0ull;}
    for(int k0=0;k0<K;k0+=16){
        {int m=tid>>2,kq=tid&3;
         float4 w4=*(const float4*)(W+(size_t)m*K+k0+4*kq);
         Ws[(4*kq+0)*68+m]=w4.x;Ws[(4*kq+1)*68+m]=w4.y;Ws[(4*kq+2)*68+m]=w4.z;Ws[(4*kq+3)*68+m]=w4.w;}
#pragma unroll
        for(int it=0;it<2;++it){int idx=it*256+tid,k=idx>>5,nq=idx&31;
            *(float4*)(Xs+k*132+4*nq)=*(const float4*)(X+(size_t)(k0+k)*N_+n0+4*nq);}
        __syncthreads();
#pragma unroll
        for(int d=0;d<16;++d){
            ulonglong2 a01=*(const ulonglong2*)(Ws+d*68+8*ty);
            ulonglong2 a23=*(const ulonglong2*)(Ws+d*68+8*ty+4);
            float4 bb=*(const float4*)(Xs+d*132+4*tx);
            u64 b0=d2(bb.x),b1=d2(bb.y),b2=d2(bb.z),b3=d2(bb.w);
            u64 av[4]={a01.x,a01.y,a23.x,a23.y};
#pragma unroll
            for(int r=0;r<4;++r){fma2(acc[r][0],av[r],b0);fma2(acc[r][1],av[r],b1);fma2(acc[r][2],av[r],b2);fma2(acc[r][3],av[r],b3);}
        }
        __syncthreads();
    }
#pragma unroll
    for(int r=0;r<4;++r){
        float l0,h0,l1,h1,l2,h2,l3,h3;
        up2(acc[r][0],l0,h0);up2(acc[r][1],l1,h1);up2(acc[r][2],l2,h2);up2(acc[r][3],l3,h3);
        *(float4*)(C+(size_t)(8*ty+2*r)*N_+4*tx)=make_float4(l0,l1,l2,l3);
        *(float4*)(C+(size_t)(8*ty+2*r+1)*N_+4*tx)=make_float4(h0,h1,h2,h3);
    }
}

__global__ __launch_bounds__(256) void k_prep1(
    const float* __restrict__ ws2, const float* __restrict__ wx2, const float* __restrict__ wy2,
    const float* __restrict__ gs1, const float* __restrict__ gx1, const float* __restrict__ gy1,
    const float* __restrict__ gs2, const float* __restrict__ bs2,
    const float* __restrict__ gx2, const float* __restrict__ bx2,
    const float* __restrict__ gy2, const float* __restrict__ by2)
{
    __shared__ __align__(16) float Fs[64*130];
    __shared__ float smu[64], sa1[64], sa2[64];
    __shared__ unsigned int s_last;
    int tid=threadIdx.x;
    int p=blockIdx.x>>5, chunk=blockIdx.x&31;
    int s0=chunk*512, b=s0>>12, n0=s0&4095;
    int ty=tid>>4, tx=tid&15;
    float acc[4][4];
#pragma unroll
    for(int r=0;r<4;++r){acc[r][0]=acc[r][1]=acc[r][2]=acc[r][3]=0.f;}
    float rs=0.f;
    const float* Z=g_z1+((size_t)(p*B_+b)*M_)*N_;
    for(int sub=0;sub<4;++sub){
        int nb=n0+sub*128;
        __syncthreads();
#pragma unroll
        for(int it=0;it<8;++it){int idx=it*256+tid,m=idx>>5,nq=idx&31;
            float4 v=*(const float4*)(Z+(size_t)m*N_+nb+4*nq);
            Fs[m*130+4*nq+0]=v.x;Fs[m*130+4*nq+1]=v.y;Fs[m*130+4*nq+2]=v.z;Fs[m*130+4*nq+3]=v.w;}
        __syncthreads();
        for(int d=0;d<128;++d){
            float a0=Fs[(4*ty+0)*130+d],a1v=Fs[(4*ty+1)*130+d],a2v=Fs[(4*ty+2)*130+d],a3=Fs[(4*ty+3)*130+d];
            float b0=Fs[(4*tx+0)*130+d],b1=Fs[(4*tx+1)*130+d],b2=Fs[(4*tx+2)*130+d],b3=Fs[(4*tx+3)*130+d];
            acc[0][0]+=a0*b0;acc[0][1]+=a0*b1;acc[0][2]+=a0*b2;acc[0][3]+=a0*b3;
            acc[1][0]+=a1v*b0;acc[1][1]+=a1v*b1;acc[1][2]+=a1v*b2;acc[1][3]+=a1v*b3;
            acc[2][0]+=a2v*b0;acc[2][1]+=a2v*b1;acc[2][2]+=a2v*b2;acc[2][3]+=a2v*b3;
            acc[3][0]+=a3*b0;acc[3][1]+=a3*b1;acc[3][2]+=a3*b2;acc[3][3]+=a3*b3;
        }
        if(tid<64){for(int i=0;i<128;++i)rs+=Fs[tid*130+i];}
    }
#pragma unroll
    for(int r=0;r<4;++r)
#pragma unroll
        for(int c=0;c<4;++c)
            atomicAdd(&g_gram1[p*4096+(4*ty+r)*64+4*tx+c],acc[r][c]);
    if(tid<64)atomicAdd(&g_sum1[p*64+tid],rs);
    __threadfence();
    if(tid==0)s_last=(atomicAdd(&g_cnt1,1u)==95u)?1u:0u;
    __syncthreads();
    if(!s_last)return;
    float* Gs=Fs; float* su=Fs+4096;
    for(int pp=0;pp<3;++pp){
        const float* w2=(pp==0)?ws2:(pp==1)?wx2:wy2;
        const float* g1=(pp==0)?gs1:(pp==1)?gx1:gy1;
        const float* g2=(pp==0)?gs2:(pp==1)?gx2:gy2;
        const float* b2=(pp==0)?bs2:(pp==1)?bx2:by2;
        __syncthreads();
        for(int i=tid;i<4096;i+=256){Gs[i]=g_gram1[pp*4096+i];g_gram1[pp*4096+i]=0.f;}
        if(tid<64){smu[tid]=g_sum1[pp*64+tid]*INVT_;g_sum1[pp*64+tid]=0.f;}
        __syncthreads();
        if(tid<64){int m=tid;float mu=smu[m];float var=Gs[m*64+m]*INVT_-mu*mu;sa1[m]=g1[m]*rsqrtf(var+EPS_);}
        __syncthreads();
        if(tid<64){
            int m=tid; float du=0.f;
            for(int k=0;k<64;++k){float u=w2[m*64+k]*sa1[k];su[m*65+k]=u;du+=u*smu[k];}
            float q=0.f;
            for(int j=0;j<64;++j){float pj=0.f;
#pragma unroll 8
                for(int k=0;k<64;++k)pj+=su[m*65+k]*Gs[j*64+k];
                q+=su[m*65+j]*pj;}
            float varz=q*INVT_-du*du;
            float a2=g2[m]*rsqrtf(varz+EPS_);
            sa2[m]=a2; g_beff[pp*64+m]=b2[m]-a2*du;
        }
        __syncthreads();
        for(int i=tid;i<4096;i+=256){int m=i>>6,k=i&63;g_w2eff[pp*4096+i]=sa2[m]*w2[i]*sa1[k];}
    }
    __syncthreads();
    if(tid==0)g_cnt1=0u;
}

__global__ __launch_bounds__(256) void k_gemm2()
{
    __shared__ __align__(16) float Ws[16*68];
    __shared__ __align__(16) float Xs[16*132];
    int z=blockIdx.y, p=z>>2, b=z&3;
    int n0=blockIdx.x*128;
    const float* W=g_w2eff+p*4096;
    const float* X=g_z1+(size_t)z*M_*N_;
    int tid=threadIdx.x, ty=tid>>5, tx=tid&31;
    u64 acc[4][4];
#pragma unroll
    for(int r=0;r<4;++r){acc[r][0]=acc[r][1]=acc[r][2]=acc[r][3]=0ull;}
    for(int k0=0;k0<64;k0+=16){
        {int m=tid>>2,kq=tid&3;
         float4 w4=*(const float4*)(W+(size_t)m*64+k0+4*kq);
         Ws[(4*kq+0)*68+m]=w4.x;Ws[(4*kq+1)*68+m]=w4.y;Ws[(4*kq+2)*68+m]=w4.z;Ws[(4*kq+3)*68+m]=w4.w;}
#pragma unroll
        for(int it=0;it<2;++it){int idx=it*256+tid,k=idx>>5,nq=idx&31;
            *(float4*)(Xs+k*132+4*nq)=*(const float4*)(X+(size_t)(k0+k)*N_+n0+4*nq);}
        __syncthreads();
#pragma unroll
        for(int d=0;d<16;++d){
            ulonglong2 a01=*(const ulonglong2*)(Ws+d*68+8*ty);
            ulonglong2 a23=*(const ulonglong2*)(Ws+d*68+8*ty+4);
            float4 bb=*(const float4*)(Xs+d*132+4*tx);
            u64 b0=d2(bb.x),b1=d2(bb.y),b2=d2(bb.z),b3=d2(bb.w);
            u64 av[4]={a01.x,a01.y,a23.x,a23.y};
#pragma unroll
            for(int r=0;r<4;++r){fma2(acc[r][0],av[r],b0);fma2(acc[r][1],av[r],b1);fma2(acc[r][2],av[r],b2);fma2(acc[r][3],av[r],b3);}
        }
        __syncthreads();
    }
    float v[8][4];
#pragma unroll
    for(int r=0;r<4;++r){
        float bl=g_beff[p*64+8*ty+2*r], bh=g_beff[p*64+8*ty+2*r+1];
        float l0,h0,l1,h1,l2,h2,l3,h3;
        up2(acc[r][0],l0,h0);up2(acc[r][1],l1,h1);up2(acc[r][2],l2,h2);up2(acc[r][3],l3,h3);
        v[2*r][0]=l0+bl;v[2*r][1]=l1+bl;v[2*r][2]=l2+bl;v[2*r][3]=l3+bl;
        v[2*r+1][0]=h0+bh;v[2*r+1][1]=h1+bh;v[2*r+1][2]=h2+bh;v[2*r+1][3]=h3+bh;
    }
    if(p==0){
#pragma unroll
        for(int r=0;r<8;++r){
            int m=8*ty+r;
            uint32_t h0=pkbf(v[r][0],v[r][1]), h1=pkbf(v[r][2],v[r][3]);
            uint32_t l0=pkbf(v[r][0]-bflo(h0),v[r][1]-bfhi(h0));
            uint32_t l1=pkbf(v[r][2]-bflo(h1),v[r][3]-bfhi(h1));
            size_t ui=(((size_t)(b*64+m))*N_+n0+4*tx)>>1;
            *(uint2*)(g_vh+ui)=make_uint2(h0,h1);
            *(uint2*)(g_vl+ui)=make_uint2(l0,l1);
        }
    }else{
        unsigned int* H=(p==1)?g_qh:g_kh;
        unsigned int* L=(p==1)?g_ql:g_kl;
#pragma unroll
        for(int c=0;c<4;++c){
            int n=n0+4*tx+c;
            uint32_t h0=pkbf(v[0][c],v[1][c]),h1=pkbf(v[2][c],v[3][c]);
            uint32_t h2=pkbf(v[4][c],v[5][c]),h3=pkbf(v[6][c],v[7][c]);
            uint32_t l0=pkbf(v[0][c]-bflo(h0),v[1][c]-bfhi(h0));
            uint32_t l1=pkbf(v[2][c]-bflo(h1),v[3][c]-bfhi(h1));
            uint32_t l2=pkbf(v[4][c]-bflo(h2),v[5][c]-bfhi(h2));
            uint32_t l3=pkbf(v[6][c]-bflo(h3),v[7][c]-bfhi(h3));
            size_t ui=(((size_t)b*N_+n)*64+8*ty)>>1;
            *(uint4*)(H+ui)=make_uint4(h0,h1,h2,h3);
            *(uint4*)(L+ui)=make_uint4(l0,l1,l2,l3);
        }
    }
}

// ---------------- HMMA flash attention: 512 thr, key-halves split across warp groups ----------------
#define AQH 0
#define AQL 18432
#define AKH 36864
#define AKL 55296
#define AVH 73728
#define AVL 91136
#define ATTN_SMEM 108544

__global__ __launch_bounds__(512, 1) void k_attn()
{
    extern __shared__ char sm_[];
    uint32_t sb=s2u(sm_);
    int tid=threadIdx.x, lane=tid&31, wid=tid>>5;
    int b=blockIdx.y, q0=blockIdx.x*128;
    int g=lane>>2, tig=lane&3;
    int wq=wid&7, jh=wid>>3;      // query group (rows wq*16), key half
    int i0=wq*16;

    {   // Q tiles -> smem (rows 128B data, 144B stride)
        const char* qh=(const char*)g_qh+((size_t)b*N_+q0)*128;
        const char* ql=(const char*)g_ql+((size_t)b*N_+q0)*128;
#pragma unroll
        for(int it=0;it<2;++it){
            int idx=it*512+tid; int row=idx>>3, ch=idx&7;
            *(uint4*)(sm_+AQH+row*144+ch*16)=*(const uint4*)(qh+row*128+ch*16);
            *(uint4*)(sm_+AQL+row*144+ch*16)=*(const uint4*)(ql+row*128+ch*16);
        }
    }
    __syncthreads();
    uint32_t qfh[4][4], qfl[4][4];
#pragma unroll
    for(int kc=0;kc<4;++kc){
        ldsm4(fraddr(sb+AQH,i0,kc*16,144,lane), qfh[kc]);
        ldsm4(fraddr(sb+AQL,i0,kc*16,144,lane), qfl[kc]);
    }
    float oacc[8][4];
#pragma unroll
    for(int nt=0;nt<8;++nt){oacc[nt][0]=oacc[nt][1]=oacc[nt][2]=oacc[nt][3]=0.f;}
    float sum0=0.f, sum1=0.f;

    for(int t=0;t<32;++t){
        __syncthreads();
        {   // K tiles + V tiles
            size_t j0=(size_t)t*128;
            const char* kh=(const char*)g_kh+((size_t)b*N_+j0)*128;
            const char* kl=(const char*)g_kl+((size_t)b*N_+j0)*128;
#pragma unroll
            for(int it=0;it<2;++it){
                int idx=it*512+tid; int row=idx>>3, ch=idx&7;
                *(uint4*)(sm_+AKH+row*144+ch*16)=*(const uint4*)(kh+row*128+ch*16);
                *(uint4*)(sm_+AKL+row*144+ch*16)=*(const uint4*)(kl+row*128+ch*16);
            }
#pragma unroll
            for(int it=0;it<2;++it){
                int idx=it*512+tid; int row=idx>>4, ch=idx&15;
                size_t gb=(((size_t)(b*64+row))*N_+j0)*2+ch*16;
                *(uint4*)(sm_+AVH+row*272+ch*16)=*(const uint4*)((const char*)g_vh+gb);
                *(uint4*)(sm_+AVL+row*272+ch*16)=*(const uint4*)((const char*)g_vl+gb);
            }
        }
        __syncthreads();

        // this warp's 64-key half; P stays in registers
        float sacc[8][4];
#pragma unroll
        for(int nt=0;nt<8;++nt){sacc[nt][0]=sacc[nt][1]=sacc[nt][2]=sacc[nt][3]=0.f;}
#pragma unroll
        for(int kc=0;kc<4;++kc){
#pragma unroll
            for(int ntp=0;ntp<4;++ntp){
                uint32_t bh[4],bl[4];
                ldsm4(fraddr(sb+AKH,jh*64+ntp*16,kc*16,144,lane),bh);
                ldsm4(fraddr(sb+AKL,jh*64+ntp*16,kc*16,144,lane),bl);
                mma16816(sacc[2*ntp],  qfh[kc],bh[0],bh[2]);
                mma16816(sacc[2*ntp+1],qfh[kc],bh[1],bh[3]);
                mma16816(sacc[2*ntp],  qfh[kc],bl[0],bl[2]);
                mma16816(sacc[2*ntp+1],qfh[kc],bl[1],bl[3]);
                mma16816(sacc[2*ntp],  qfl[kc],bh[0],bh[2]);
                mma16816(sacc[2*ntp+1],qfl[kc],bh[1],bh[3]);
            }
        }
#pragma unroll
        for(int kc2=0;kc2<4;++kc2){
            float e0=__expf(sacc[2*kc2][0]),  e1=__expf(sacc[2*kc2][1]);
            float e2=__expf(sacc[2*kc2][2]),  e3=__expf(sacc[2*kc2][3]);
            float f0=__expf(sacc[2*kc2+1][0]),f1=__expf(sacc[2*kc2+1][1]);
            float f2=__expf(sacc[2*kc2+1][2]),f3=__expf(sacc[2*kc2+1][3]);
            sum0+=(e0+e1)+(f0+f1); sum1+=(e2+e3)+(f2+f3);
            uint32_t ah[4], al[4];
            ah[0]=pkbf(e0,e1); ah[1]=pkbf(e2,e3); ah[2]=pkbf(f0,f1); ah[3]=pkbf(f2,f3);
            al[0]=pkbf(e0-bflo(ah[0]),e1-bfhi(ah[0]));
            al[1]=pkbf(e2-bflo(ah[1]),e3-bfhi(ah[1]));
            al[2]=pkbf(f0-bflo(ah[2]),f1-bfhi(ah[2]));
            al[3]=pkbf(f2-bflo(ah[3]),f3-bfhi(ah[3]));
#pragma unroll
            for(int ntp2=0;ntp2<4;++ntp2){
                uint32_t bh[4],bl[4];
                ldsm4(fraddr(sb+AVH,ntp2*16,jh*64+kc2*16,272,lane),bh);
                ldsm4(fraddr(sb+AVL,ntp2*16,jh*64+kc2*16,272,lane),bl);
                mma16816(oacc[2*ntp2],  ah,bh[0],bh[2]);
                mma16816(oacc[2*ntp2+1],ah,bh[1],bh[3]);
                mma16816(oacc[2*ntp2],  ah,bl[0],bl[2]);
                mma16816(oacc[2*ntp2+1],ah,bl[1],bl[3]);
                mma16816(oacc[2*ntp2],  al,bh[0],bh[2]);
                mma16816(oacc[2*ntp2+1],al,bh[1],bh[3]);
            }
        }
    }

    // combine the two key-half partials (no-max softmax -> plain add), then normalize+store
    sum0+=__shfl_xor_sync(0xffffffffu,sum0,1);
    sum0+=__shfl_xor_sync(0xffffffffu,sum0,2);
    sum1+=__shfl_xor_sync(0xffffffffu,sum1,1);
    sum1+=__shfl_xor_sync(0xffffffffu,sum1,2);
    float* Os=(float*)sm_;               // 128*64 floats (reuses dead Q region)
    float* Ls=(float*)(sm_+32768);       // 128 floats (jh=1 half sums)
    int r_lo=i0+g, r_hi=i0+g+8;
    __syncthreads();
    if(jh==1){
        if(tig==0){ Ls[r_lo]=sum0; Ls[r_hi]=sum1; }
#pragma unroll
        for(int nt=0;nt<8;++nt){
            int c0=nt*8+tig*2;
            Os[r_lo*64+c0]=oacc[nt][0]; Os[r_lo*64+c0+1]=oacc[nt][1];
            Os[r_hi*64+c0]=oacc[nt][2]; Os[r_hi*64+c0+1]=oacc[nt][3];
        }
    }
    __syncthreads();
    if(jh==0){
        float inv0=1.f/(sum0+Ls[r_lo]);
        float inv1=1.f/(sum1+Ls[r_hi]);
        int n_lo=q0+r_lo, n_hi=q0+r_hi;
#pragma unroll
        for(int nt=0;nt<8;++nt){
            int c0=nt*8+tig*2;
            g_fout[((size_t)(b*64)+c0  )*N_+n_lo]=(oacc[nt][0]+Os[r_lo*64+c0  ])*inv0;
            g_fout[((size_t)(b*64)+c0+1)*N_+n_lo]=(oacc[nt][1]+Os[r_lo*64+c0+1])*inv0;
            g_fout[((size_t)(b*64)+c0  )*N_+n_hi]=(oacc[nt][2]+Os[r_hi*64+c0  ])*inv1;
            g_fout[((size_t)(b*64)+c0+1)*N_+n_hi]=(oacc[nt][3]+Os[r_hi*64+c0+1])*inv1;
        }
    }
}

__global__ __launch_bounds__(256) void k_gramf()
{
    __shared__ float Fs[64*129];
    int chunk=blockIdx.x;
    int b=chunk>>4, nbase=(chunk&15)*256;
    int tid=threadIdx.x, ty=tid>>4, tx=tid&15;
    float acc[4][4];
#pragma unroll
    for(int r=0;r<4;++r){acc[r][0]=acc[r][1]=acc[r][2]=acc[r][3]=0.f;}
    float rs=0.f;
    for(int sub=0;sub<2;++sub){
        int n0=nbase+sub*128;
        __syncthreads();
#pragma unroll
        for(int it=0;it<8;++it){int idx=it*256+tid,m=idx>>5,nq=idx&31;
            float4 v=*(const float4*)(g_fout+((size_t)b*M_+m)*N_+n0+4*nq);
            Fs[m*129+4*nq+0]=v.x;Fs[m*129+4*nq+1]=v.y;Fs[m*129+4*nq+2]=v.z;Fs[m*129+4*nq+3]=v.w;}
        __syncthreads();
        for(int d=0;d<128;++d){
            float a0=Fs[(4*ty+0)*129+d],a1=Fs[(4*ty+1)*129+d],a2=Fs[(4*ty+2)*129+d],a3=Fs[(4*ty+3)*129+d];
            float b0=Fs[(4*tx+0)*129+d],b1=Fs[(4*tx+1)*129+d],b2=Fs[(4*tx+2)*129+d],b3=Fs[(4*tx+3)*129+d];
            acc[0][0]+=a0*b0;acc[0][1]+=a0*b1;acc[0][2]+=a0*b2;acc[0][3]+=a0*b3;
            acc[1][0]+=a1*b0;acc[1][1]+=a1*b1;acc[1][2]+=a1*b2;acc[1][3]+=a1*b3;
            acc[2][0]+=a2*b0;acc[2][1]+=a2*b1;acc[2][2]+=a2*b2;acc[2][3]+=a2*b3;
            acc[3][0]+=a3*b0;acc[3][1]+=a3*b1;acc[3][2]+=a3*b2;acc[3][3]+=a3*b3;
        }
        if(tid<64){for(int i=0;i<128;++i)rs+=Fs[tid*129+i];}
    }
#pragma unroll
    for(int r=0;r<4;++r)
#pragma unroll
        for(int c=0;c<4;++c)
            atomicAdd(&g_gramf[(4*ty+r)*64+4*tx+c],acc[r][c]);
    if(tid<64)atomicAdd(&g_sumf[tid],rs);
}

__global__ void k_bnup(const float* __restrict__ wu, const float* __restrict__ gu,
                       const float* __restrict__ bu)
{
    __shared__ float s1[64], s2[64];
    int c=blockIdx.x, t=threadIdx.x;
    float tmp=0.f;
#pragma unroll 8
    for(int k=0;k<64;++k)tmp+=g_gramf[t*64+k]*wu[c*64+k];
    float wt=wu[c*64+t];
    s1[t]=wt*tmp; s2[t]=wt*g_sumf[t];
    __syncthreads();
    for(int off=32;off;off>>=1){
        if(t<off){s1[t]+=s1[t+off];s2[t]+=s2[t+off];}
        __syncthreads();
    }
    if(t==0){
        float mean=s2[0]*INVT_;
        float var=s1[0]*INVT_-mean*mean;
        float a=gu[c]*rsqrtf(var+EPS_);
        g_au[c]=a; g_bu[c]=bu[c]-a*mean;
    }
}

__global__ __launch_bounds__(256) void k_final(const float* __restrict__ x,
                                               const float* __restrict__ wu,
                                               float* __restrict__ out)
{
    __shared__ __align__(16) float Ws[16*68];
    __shared__ __align__(16) float Xs[16*132];
    int n0=blockIdx.x*128, c0=blockIdx.y*64, b=blockIdx.z;
    const float* F=g_fout+(size_t)b*M_*N_;
    int tid=threadIdx.x, ty=tid>>5, tx=tid&31;
    if(blockIdx.x==0&&blockIdx.y==0&&blockIdx.z==0){
        for(int i=tid;i<4096;i+=256)g_gramf[i]=0.f;
        if(tid<64)g_sumf[tid]=0.f;
    }
    u64 acc[4][4];
#pragma unroll
    for(int r=0;r<4;++r){acc[r][0]=acc[r][1]=acc[r][2]=acc[r][3]=0ull;}
    for(int k0=0;k0<64;k0+=16){
        {int m=tid>>2,kq=tid&3;
         float4 w4=*(const float4*)(wu+(size_t)(c0+m)*64+k0+4*kq);
         Ws[(4*kq+0)*68+m]=w4.x;Ws[(4*kq+1)*68+m]=w4.y;Ws[(4*kq+2)*68+m]=w4.z;Ws[(4*kq+3)*68+m]=w4.w;}
#pragma unroll
        for(int it=0;it<2;++it){int idx=it*256+tid,k=idx>>5,nq=idx&31;
            *(float4*)(Xs+k*132+4*nq)=*(const float4*)(F+(size_t)(k0+k)*N_+n0+4*nq);}
        __syncthreads();
#pragma unroll
        for(int d=0;d<16;++d){
            ulonglong2 a01=*(const ulonglong2*)(Ws+d*68+8*ty);
            ulonglong2 a23=*(const ulonglong2*)(Ws+d*68+8*ty+4);
            float4 bb=*(const float4*)(Xs+d*132+4*tx);
            u64 b0=d2(bb.x),b1=d2(bb.y),b2=d2(bb.z),b3=d2(bb.w);
            u64 av[4]={a01.x,a01.y,a23.x,a23.y};
#pragma unroll
            for(int r=0;r<4;++r){fma2(acc[r][0],av[r],b0);fma2(acc[r][1],av[r],b1);fma2(acc[r][2],av[r],b2);fma2(acc[r][3],av[r],b3);}
        }
        __syncthreads();
    }
#pragma unroll
    for(int r=0;r<4;++r){
        float l0,h0,l1,h1,l2,h2,l3,h3;
        up2(acc[r][0],l0,h0);up2(acc[r][1],l1,h1);up2(acc[r][2],l2,h2);up2(acc[r][3],l3,h3);
        int cl=c0+8*ty+2*r, ch=cl+1;
        float al=g_au[cl],bl=g_bu[cl],ah=g_au[ch],bh=g_bu[ch];
        size_t ol=((size_t)b*CX+cl)*N_+n0+4*tx;
        size_t oh=((size_t)b*CX+ch)*N_+n0+4*tx;
        float4 xl=*(const float4*)(x+ol);
        float4 xh=*(const float4*)(x+oh);
        *(float4*)(out+ol)=make_float4(xl.x+al*l0+bl,xl.y+al*l1+bl,xl.z+al*l2+bl,xl.w+al*l3+bl);
        *(float4*)(out+oh)=make_float4(xh.x+ah*h0+bh,xh.y+ah*h1+bh,xh.z+ah*h2+bh,xh.w+ah*h3+bh);
    }
}

extern "C" void kernel_launch(void* const* d_in, const int* in_sizes, int n_in,
                              void* d_out, int out_size)
{
    const float* x   = (const float*)d_in[0];
    const float* y   = (const float*)d_in[1];
    const float* ws1 = (const float*)d_in[2];
    const float* gs1 = (const float*)d_in[3];
    const float* ws2 = (const float*)d_in[5];
    const float* gs2 = (const float*)d_in[6];
    const float* bs2 = (const float*)d_in[7];
    const float* wx1 = (const float*)d_in[8];
    const float* gx1 = (const float*)d_in[9];
    const float* wx2 = (const float*)d_in[11];
    const float* gx2 = (const float*)d_in[12];
    const float* bx2 = (const float*)d_in[13];
    const float* wy1 = (const float*)d_in[14];
    const float* gy1 = (const float*)d_in[15];
    const float* wy2 = (const float*)d_in[17];
    const float* gy2 = (const float*)d_in[18];
    const float* by2 = (const float*)d_in[19];
    const float* wu  = (const float*)d_in[20];
    const float* gu  = (const float*)d_in[21];
    const float* bu  = (const float*)d_in[22];
    float* out = (float*)d_out;

    cudaFuncSetAttribute(k_attn, cudaFuncAttributeMaxDynamicSharedMemorySize, ATTN_SMEM);

    k_gemm1<<<dim3(32, B_, 3), 256>>>(x, y, ws1, wx1, wy1);
    k_prep1<<<96, 256>>>(ws2, wx2, wy2, gs1, gx1, gy1,
                         gs2, bs2, gx2, bx2, gy2, by2);
    k_gemm2<<<dim3(32, 12), 256>>>();
    k_attn<<<dim3(32, B_), 512, ATTN_SMEM>>>();   // launch #4 -> profiled
    k_gramf<<<64, 256>>>();
    k_bnup<<<512, 64>>>(wu, gu, bu);
    k_final<<<dim3(32, 8, B_), 256>>>(x, wu, out);
}

// round 15
// speedup vs baseline: 1.0495x; 1.0495x over previous
#include <cuda_runtime.h>
#include <cuda_bf16.h>
#include <cstdint>

#define B_ 4
#define CX 512
#define CY 256
#define M_ 64
#define N_ 4096
#define EPS_ 1e-5f
#define INVT_ (1.0f / 16384.0f)

typedef unsigned long long u64;

__device__ __forceinline__ u64 d2(float v){u64 r;asm("mov.b64 %0,{%1,%1};":"=l"(r):"f"(v));return r;}
__device__ __forceinline__ void up2(u64 v,float&a,float&b){asm("mov.b64 {%0,%1},%2;":"=f"(a),"=f"(b):"l"(v));}
__device__ __forceinline__ void fma2(u64&d,u64 a,u64 b){asm("fma.rn.f32x2 %0,%1,%2,%0;":"+l"(d):"l"(a),"l"(b));}
__device__ __forceinline__ uint32_t pkbf(float lo,float hi){uint32_t r;asm("cvt.rn.bf16x2.f32 %0, %1, %2;":"=r"(r):"f"(hi),"f"(lo));return r;}
__device__ __forceinline__ float bflo(uint32_t p){return __uint_as_float(p<<16);}
__device__ __forceinline__ float bfhi(uint32_t p){return __uint_as_float(p&0xffff0000u);}
__device__ __forceinline__ uint32_t s2u(const void*p){uint32_t a;asm("{ .reg .u64 t; cvta.to.shared.u64 t, %1; cvt.u32.u64 %0, t; }":"=r"(a):"l"(p));return a;}

__device__ __forceinline__ void ldsm4(uint32_t a, uint32_t* r){
    asm volatile("ldmatrix.sync.aligned.m8n8.x4.shared.b16 {%0,%1,%2,%3}, [%4];"
        :"=r"(r[0]),"=r"(r[1]),"=r"(r[2]),"=r"(r[3]):"r"(a));
}
__device__ __forceinline__ void mma16816(float* c, const uint32_t* a, uint32_t b0, uint32_t b1){
    asm volatile("mma.sync.aligned.m16n8k16.row.col.f32.bf16.bf16.f32 {%0,%1,%2,%3},{%4,%5,%6,%7},{%8,%9},{%0,%1,%2,%3};"
        :"+f"(c[0]),"+f"(c[1]),"+f"(c[2]),"+f"(c[3])
        :"r"(a[0]),"r"(a[1]),"r"(a[2]),"r"(a[3]),"r"(b0),"r"(b1));
}
__device__ __forceinline__ uint32_t fraddr(uint32_t base, int r0, int k0, int stride, int lane){
    int row = r0 + (lane&7) + ((lane&8)?8:0);
    int col = k0 + ((lane&16)?8:0);
    return base + row*stride + col*2;
}

__device__ __align__(16) float g_z1[3*B_*M_*N_];
__device__ __align__(16) float g_fout[B_*M_*N_];
__device__ __align__(16) unsigned int g_xth[B_*N_*256], g_xtl[B_*N_*256]; // x^T [b][n][512c] bf16
__device__ __align__(16) unsigned int g_yth[B_*N_*128], g_ytl[B_*N_*128]; // y^T [b][n][256c] bf16
__device__ __align__(16) unsigned int g_qh[B_*N_*32], g_ql[B_*N_*32];   // [b][n][64m] bf16
__device__ __align__(16) unsigned int g_kh[B_*N_*32], g_kl[B_*N_*32];   // [b][n][64m] bf16
__device__ __align__(16) unsigned int g_vh[B_*M_*N_/2], g_vl[B_*M_*N_/2]; // [b][c][n] bf16
__device__ float g_gram1[3*64*64];
__device__ float g_sum1[192];
__device__ unsigned int g_cnt1;
__device__ __align__(16) float g_w2eff[3*64*64];
__device__ float g_beff[192];
__device__ float g_gramf[64*64];
__device__ float g_sumf[64];
__device__ float g_au[512], g_bu[512];

// ---------------- transpose+split x,y -> bf16 hi/lo [b][n][c] ----------------
__global__ __launch_bounds__(256) void k_splitx(const float* __restrict__ x, const float* __restrict__ y)
{
    __shared__ float Ts[32*132];
    int b=blockIdx.z, ct=blockIdx.y, n0=blockIdx.x*128;
    int isy=(ct>=16);
    int c0=(isy?ct-16:ct)*32;
    int K=isy?256:512;
    const float* S=isy?(y+((size_t)b*CY+c0)*N_):(x+((size_t)b*CX+c0)*N_);
    unsigned int* H=isy?g_yth:g_xth;
    unsigned int* L=isy?g_ytl:g_xtl;
    int tid=threadIdx.x;
#pragma unroll
    for(int it=0;it<4;++it){int idx=it*256+tid,c=idx>>5,nq=idx&31;
        *(float4*)(Ts+c*132+4*nq)=*(const float4*)(S+(size_t)c*N_+n0+4*nq);}
    __syncthreads();
#pragma unroll
    for(int it=0;it<2;++it){
        int idx=it*256+tid, n=idx>>2, cq=idx&3;
        uint32_t h[4],l[4];
#pragma unroll
        for(int u=0;u<4;++u){
            float v0=Ts[(cq*8+2*u)*132+n], v1=Ts[(cq*8+2*u+1)*132+n];
            h[u]=pkbf(v0,v1);
            l[u]=pkbf(v0-bflo(h[u]),v1-bfhi(h[u]));
        }
        size_t ui=(((size_t)b*N_+n0+n)*K + c0+cq*8)>>1;
        *(uint4*)(H+ui)=make_uint4(h[0],h[1],h[2],h[3]);
        *(uint4*)(L+ui)=make_uint4(l[0],l[1],l[2],l[3]);
    }
}

// ---------------- stage-1 conv1x1 via HMMA (bf16 3-split) ----------------
#define G1X 0
#define G1XL 10240
#define G1W 20480
#define G1WL 25600
__global__ __launch_bounds__(256) void k_gemm1h(
    const float* __restrict__ ws1, const float* __restrict__ wx1, const float* __restrict__ wy1)
{
    __shared__ __align__(16) char s[30720];
    uint32_t sb=s2u(s);
    int p=blockIdx.z, b=blockIdx.y, n0=blockIdx.x*128;
    const float* W=(p==0)?ws1:(p==1)?wx1:wy1;
    int K=(p==2)?256:512;
    const unsigned int* H=(p==2)?g_yth:g_xth;
    const unsigned int* L=(p==2)?g_ytl:g_xtl;
    int tid=threadIdx.x, lane=tid&31, wid=tid>>5;
    int mt=wid&3, nh=wid>>2;
    float cacc[8][4];
#pragma unroll
    for(int i=0;i<8;++i){cacc[i][0]=cacc[i][1]=cacc[i][2]=cacc[i][3]=0.f;}

    for(int k0=0;k0<K;k0+=32){
        __syncthreads();
#pragma unroll
        for(int it=0;it<4;++it){   // W chunk 64x32 fp32 -> bf16 hi/lo
            int idx=it*256+tid, m=idx>>4, kq=idx&15;
            float2 w=*(const float2*)(W+(size_t)m*K+k0+2*kq);
            uint32_t h=pkbf(w.x,w.y);
            uint32_t l=pkbf(w.x-bflo(h),w.y-bfhi(h));
            *(uint32_t*)(s+G1W+m*80+kq*4)=h;
            *(uint32_t*)(s+G1WL+m*80+kq*4)=l;
        }
#pragma unroll
        for(int it=0;it<2;++it){   // X^T chunk: 128 rows x 32c bf16
            int idx=it*256+tid, n=idx>>2, q=idx&3;
            size_t ui=(((size_t)b*N_+n0+n)*K+k0)>>1;
            *(uint4*)(s+G1X+n*80+q*16)=*(const uint4*)(H+ui+q*4);
            *(uint4*)(s+G1XL+n*80+q*16)=*(const uint4*)(L+ui+q*4);
        }
        __syncthreads();
        uint32_t ah[2][4], al[2][4];
#pragma unroll
        for(int ks=0;ks<2;++ks){
            ldsm4(fraddr(sb+G1W, mt*16, ks*16, 80, lane), ah[ks]);
            ldsm4(fraddr(sb+G1WL,mt*16, ks*16, 80, lane), al[ks]);
        }
#pragma unroll
        for(int ks=0;ks<2;++ks){
#pragma unroll
            for(int ns=0;ns<4;++ns){
                uint32_t bh[4],bl[4];
                ldsm4(fraddr(sb+G1X, nh*64+ns*16, ks*16, 80, lane), bh);
                ldsm4(fraddr(sb+G1XL,nh*64+ns*16, ks*16, 80, lane), bl);
                mma16816(cacc[2*ns],  ah[ks],bh[0],bh[2]);
                mma16816(cacc[2*ns+1],ah[ks],bh[1],bh[3]);
                mma16816(cacc[2*ns],  ah[ks],bl[0],bl[2]);
                mma16816(cacc[2*ns+1],ah[ks],bl[1],bl[3]);
                mma16816(cacc[2*ns],  al[ks],bh[0],bh[2]);
                mma16816(cacc[2*ns+1],al[ks],bh[1],bh[3]);
            }
        }
    }
    int g=lane>>2, t=lane&3;
    float* C=g_z1+((size_t)(p*B_+b)*64)*N_;
#pragma unroll
    for(int nt=0;nt<8;++nt){
        int n=n0+nh*64+(nt>>1)*16+(nt&1)*8+2*t;
        *(float2*)(C+(size_t)(mt*16+g)*N_+n)  =make_float2(cacc[nt][0],cacc[nt][1]);
        *(float2*)(C+(size_t)(mt*16+g+8)*N_+n)=make_float2(cacc[nt][2],cacc[nt][3]);
    }
}

// ---------------- z1 gram + BN folds (unchanged) ----------------
__global__ __launch_bounds__(256) void k_prep1(
    const float* __restrict__ ws2, const float* __restrict__ wx2, const float* __restrict__ wy2,
    const float* __restrict__ gs1, const float* __restrict__ gx1, const float* __restrict__ gy1,
    const float* __restrict__ gs2, const float* __restrict__ bs2,
    const float* __restrict__ gx2, const float* __restrict__ bx2,
    const float* __restrict__ gy2, const float* __restrict__ by2)
{
    __shared__ __align__(16) float Fs[64*130];
    __shared__ float smu[64], sa1[64], sa2[64];
    __shared__ unsigned int s_last;
    int tid=threadIdx.x;
    int p=blockIdx.x>>5, chunk=blockIdx.x&31;
    int s0=chunk*512, b=s0>>12, n0=s0&4095;
    int ty=tid>>4, tx=tid&15;
    float acc[4][4];
#pragma unroll
    for(int r=0;r<4;++r){acc[r][0]=acc[r][1]=acc[r][2]=acc[r][3]=0.f;}
    float rs=0.f;
    const float* Z=g_z1+((size_t)(p*B_+b)*M_)*N_;
    for(int sub=0;sub<4;++sub){
        int nb=n0+sub*128;
        __syncthreads();
#pragma unroll
        for(int it=0;it<8;++it){int idx=it*256+tid,m=idx>>5,nq=idx&31;
            float4 v=*(const float4*)(Z+(size_t)m*N_+nb+4*nq);
            Fs[m*130+4*nq+0]=v.x;Fs[m*130+4*nq+1]=v.y;Fs[m*130+4*nq+2]=v.z;Fs[m*130+4*nq+3]=v.w;}
        __syncthreads();
        for(int d=0;d<128;++d){
            float a0=Fs[(4*ty+0)*130+d],a1v=Fs[(4*ty+1)*130+d],a2v=Fs[(4*ty+2)*130+d],a3=Fs[(4*ty+3)*130+d];
            float b0=Fs[(4*tx+0)*130+d],b1=Fs[(4*tx+1)*130+d],b2=Fs[(4*tx+2)*130+d],b3=Fs[(4*tx+3)*130+d];
            acc[0][0]+=a0*b0;acc[0][1]+=a0*b1;acc[0][2]+=a0*b2;acc[0][3]+=a0*b3;
            acc[1][0]+=a1v*b0;acc[1][1]+=a1v*b1;acc[1][2]+=a1v*b2;acc[1][3]+=a1v*b3;
            acc[2][0]+=a2v*b0;acc[2][1]+=a2v*b1;acc[2][2]+=a2v*b2;acc[2][3]+=a2v*b3;
            acc[3][0]+=a3*b0;acc[3][1]+=a3*b1;acc[3][2]+=a3*b2;acc[3][3]+=a3*b3;
        }
        if(tid<64){for(int i=0;i<128;++i)rs+=Fs[tid*130+i];}
    }
#pragma unroll
    for(int r=0;r<4;++r)
#pragma unroll
        for(int c=0;c<4;++c)
            atomicAdd(&g_gram1[p*4096+(4*ty+r)*64+4*tx+c],acc[r][c]);
    if(tid<64)atomicAdd(&g_sum1[p*64+tid],rs);
    __threadfence();
    if(tid==0)s_last=(atomicAdd(&g_cnt1,1u)==95u)?1u:0u;
    __syncthreads();
    if(!s_last)return;
    float* Gs=Fs; float* su=Fs+4096;
    for(int pp=0;pp<3;++pp){
        const float* w2=(pp==0)?ws2:(pp==1)?wx2:wy2;
        const float* g1=(pp==0)?gs1:(pp==1)?gx1:gy1;
        const float* g2=(pp==0)?gs2:(pp==1)?gx2:gy2;
        const float* b2=(pp==0)?bs2:(pp==1)?bx2:by2;
        __syncthreads();
        for(int i=tid;i<4096;i+=256){Gs[i]=g_gram1[pp*4096+i];g_gram1[pp*4096+i]=0.f;}
        if(tid<64){smu[tid]=g_sum1[pp*64+tid]*INVT_;g_sum1[pp*64+tid]=0.f;}
        __syncthreads();
        if(tid<64){int m=tid;float mu=smu[m];float var=Gs[m*64+m]*INVT_-mu*mu;sa1[m]=g1[m]*rsqrtf(var+EPS_);}
        __syncthreads();
        if(tid<64){
            int m=tid; float du=0.f;
            for(int k=0;k<64;++k){float u=w2[m*64+k]*sa1[k];su[m*65+k]=u;du+=u*smu[k];}
            float q=0.f;
            for(int j=0;j<64;++j){float pj=0.f;
#pragma unroll 8
                for(int k=0;k<64;++k)pj+=su[m*65+k]*Gs[j*64+k];
                q+=su[m*65+j]*pj;}
            float varz=q*INVT_-du*du;
            float a2=g2[m]*rsqrtf(varz+EPS_);
            sa2[m]=a2; g_beff[pp*64+m]=b2[m]-a2*du;
        }
        __syncthreads();
        for(int i=tid;i<4096;i+=256){int m=i>>6,k=i&63;g_w2eff[pp*4096+i]=sa2[m]*w2[i]*sa1[k];}
    }
    __syncthreads();
    if(tid==0)g_cnt1=0u;
}

__global__ __launch_bounds__(256) void k_gemm2()
{
    __shared__ __align__(16) float Ws[16*68];
    __shared__ __align__(16) float Xs[16*132];
    int z=blockIdx.y, p=z>>2, b=z&3;
    int n0=blockIdx.x*128;
    const float* W=g_w2eff+p*4096;
    const float* X=g_z1+(size_t)z*M_*N_;
    int tid=threadIdx.x, ty=tid>>5, tx=tid&31;
    u64 acc[4][4];
#pragma unroll
    for(int r=0;r<4;++r){acc[r][0]=acc[r][1]=acc[r][2]=acc[r][3]=0ull;}
    for(int k0=0;k0<64;k0+=16){
        {int m=tid>>2,kq=tid&3;
         float4 w4=*(const float4*)(W+(size_t)m*64+k0+4*kq);
         Ws[(4*kq+0)*68+m]=w4.x;Ws[(4*kq+1)*68+m]=w4.y;Ws[(4*kq+2)*68+m]=w4.z;Ws[(4*kq+3)*68+m]=w4.w;}
#pragma unroll
        for(int it=0;it<2;++it){int idx=it*256+tid,k=idx>>5,nq=idx&31;
            *(float4*)(Xs+k*132+4*nq)=*(const float4*)(X+(size_t)(k0+k)*N_+n0+4*nq);}
        __syncthreads();
#pragma unroll
        for(int d=0;d<16;++d){
            ulonglong2 a01=*(const ulonglong2*)(Ws+d*68+8*ty);
            ulonglong2 a23=*(const ulonglong2*)(Ws+d*68+8*ty+4);
            float4 bb=*(const float4*)(Xs+d*132+4*tx);
            u64 b0=d2(bb.x),b1=d2(bb.y),b2=d2(bb.z),b3=d2(bb.w);
            u64 av[4]={a01.x,a01.y,a23.x,a23.y};
#pragma unroll
            for(int r=0;r<4;++r){fma2(acc[r][0],av[r],b0);fma2(acc[r][1],av[r],b1);fma2(acc[r][2],av[r],b2);fma2(acc[r][3],av[r],b3);}
        }
        __syncthreads();
    }
    float v[8][4];
#pragma unroll
    for(int r=0;r<4;++r){
        float bl=g_beff[p*64+8*ty+2*r], bh=g_beff[p*64+8*ty+2*r+1];
        float l0,h0,l1,h1,l2,h2,l3,h3;
        up2(acc[r][0],l0,h0);up2(acc[r][1],l1,h1);up2(acc[r][2],l2,h2);up2(acc[r][3],l3,h3);
        v[2*r][0]=l0+bl;v[2*r][1]=l1+bl;v[2*r][2]=l2+bl;v[2*r][3]=l3+bl;
        v[2*r+1][0]=h0+bh;v[2*r+1][1]=h1+bh;v[2*r+1][2]=h2+bh;v[2*r+1][3]=h3+bh;
    }
    if(p==0){
#pragma unroll
        for(int r=0;r<8;++r){
            int m=8*ty+r;
            uint32_t h0=pkbf(v[r][0],v[r][1]), h1=pkbf(v[r][2],v[r][3]);
            uint32_t l0=pkbf(v[r][0]-bflo(h0),v[r][1]-bfhi(h0));
            uint32_t l1=pkbf(v[r][2]-bflo(h1),v[r][3]-bfhi(h1));
            size_t ui=(((size_t)(b*64+m))*N_+n0+4*tx)>>1;
            *(uint2*)(g_vh+ui)=make_uint2(h0,h1);
            *(uint2*)(g_vl+ui)=make_uint2(l0,l1);
        }
    }else{
        unsigned int* H=(p==1)?g_qh:g_kh;
        unsigned int* L=(p==1)?g_ql:g_kl;
#pragma unroll
        for(int c=0;c<4;++c){
            int n=n0+4*tx+c;
            uint32_t h0=pkbf(v[0][c],v[1][c]),h1=pkbf(v[2][c],v[3][c]);
            uint32_t h2=pkbf(v[4][c],v[5][c]),h3=pkbf(v[6][c],v[7][c]);
            uint32_t l0=pkbf(v[0][c]-bflo(h0),v[1][c]-bfhi(h0));
            uint32_t l1=pkbf(v[2][c]-bflo(h1),v[3][c]-bfhi(h1));
            uint32_t l2=pkbf(v[4][c]-bflo(h2),v[5][c]-bfhi(h2));
            uint32_t l3=pkbf(v[6][c]-bflo(h3),v[7][c]-bfhi(h3));
            size_t ui=(((size_t)b*N_+n)*64+8*ty)>>1;
            *(uint4*)(H+ui)=make_uint4(h0,h1,h2,h3);
            *(uint4*)(L+ui)=make_uint4(l0,l1,l2,l3);
        }
    }
}

// ---------------- HMMA flash attention (256 thr, register P) + fused gram ----------------
#define AQH 0
#define AQL 18432
#define AKH 36864
#define AKL 55296
#define AVH 73728
#define AVL 91136
#define ATTN_SMEM 108544

__global__ __launch_bounds__(256, 1) void k_attn()
{
    extern __shared__ char sm_[];
    uint32_t sb=s2u(sm_);
    int tid=threadIdx.x, lane=tid&31, wid=tid>>5;
    int b=blockIdx.y, q0=blockIdx.x*128;
    int g=lane>>2;

    {
        const char* qh=(const char*)g_qh+((size_t)b*N_+q0)*128;
        const char* ql=(const char*)g_ql+((size_t)b*N_+q0)*128;
#pragma unroll
        for(int it=0;it<4;++it){
            int idx=it*256+tid; int row=idx>>3, ch=idx&7;
            *(uint4*)(sm_+AQH+row*144+ch*16)=*(const uint4*)(qh+row*128+ch*16);
            *(uint4*)(sm_+AQL+row*144+ch*16)=*(const uint4*)(ql+row*128+ch*16);
        }
    }
    __syncthreads();
    int i0=wid*16;
    uint32_t qfh[4][4], qfl[4][4];
#pragma unroll
    for(int kc=0;kc<4;++kc){
        ldsm4(fraddr(sb+AQH,i0,kc*16,144,lane), qfh[kc]);
        ldsm4(fraddr(sb+AQL,i0,kc*16,144,lane), qfl[kc]);
    }
    float oacc[8][4];
#pragma unroll
    for(int nt=0;nt<8;++nt){oacc[nt][0]=oacc[nt][1]=oacc[nt][2]=oacc[nt][3]=0.f;}
    float sum0=0.f, sum1=0.f;

    for(int t=0;t<32;++t){
        __syncthreads();
        {
            size_t j0=(size_t)t*128;
            const char* kh=(const char*)g_kh+((size_t)b*N_+j0)*128;
            const char* kl=(const char*)g_kl+((size_t)b*N_+j0)*128;
#pragma unroll
            for(int it=0;it<4;++it){
                int idx=it*256+tid; int row=idx>>3, ch=idx&7;
                *(uint4*)(sm_+AKH+row*144+ch*16)=*(const uint4*)(kh+row*128+ch*16);
                *(uint4*)(sm_+AKL+row*144+ch*16)=*(const uint4*)(kl+row*128+ch*16);
            }
#pragma unroll
            for(int it=0;it<4;++it){
                int idx=it*256+tid; int row=idx>>4, ch=idx&15;
                size_t gb=(((size_t)(b*64+row))*N_+j0)*2+ch*16;
                *(uint4*)(sm_+AVH+row*272+ch*16)=*(const uint4*)((const char*)g_vh+gb);
                *(uint4*)(sm_+AVL+row*272+ch*16)=*(const uint4*)((const char*)g_vl+gb);
            }
        }
        __syncthreads();

#pragma unroll
        for(int jh=0;jh<2;++jh){
            float sacc[8][4];
#pragma unroll
            for(int nt=0;nt<8;++nt){sacc[nt][0]=sacc[nt][1]=sacc[nt][2]=sacc[nt][3]=0.f;}
#pragma unroll
            for(int kc=0;kc<4;++kc){
#pragma unroll
                for(int ntp=0;ntp<4;++ntp){
                    uint32_t bh[4],bl[4];
                    ldsm4(fraddr(sb+AKH,jh*64+ntp*16,kc*16,144,lane),bh);
                    ldsm4(fraddr(sb+AKL,jh*64+ntp*16,kc*16,144,lane),bl);
                    mma16816(sacc[2*ntp],  qfh[kc],bh[0],bh[2]);
                    mma16816(sacc[2*ntp+1],qfh[kc],bh[1],bh[3]);
                    mma16816(sacc[2*ntp],  qfh[kc],bl[0],bl[2]);
                    mma16816(sacc[2*ntp+1],qfh[kc],bl[1],bl[3]);
                    mma16816(sacc[2*ntp],  qfl[kc],bh[0],bh[2]);
                    mma16816(sacc[2*ntp+1],qfl[kc],bh[1],bh[3]);
                }
            }
#pragma unroll
            for(int kc2=0;kc2<4;++kc2){
                float e0=__expf(sacc[2*kc2][0]),  e1=__expf(sacc[2*kc2][1]);
                float e2=__expf(sacc[2*kc2][2]),  e3=__expf(sacc[2*kc2][3]);
                float f0=__expf(sacc[2*kc2+1][0]),f1=__expf(sacc[2*kc2+1][1]);
                float f2=__expf(sacc[2*kc2+1][2]),f3=__expf(sacc[2*kc2+1][3]);
                sum0+=(e0+e1)+(f0+f1); sum1+=(e2+e3)+(f2+f3);
                uint32_t ah[4], al[4];
                ah[0]=pkbf(e0,e1); ah[1]=pkbf(e2,e3); ah[2]=pkbf(f0,f1); ah[3]=pkbf(f2,f3);
                al[0]=pkbf(e0-bflo(ah[0]),e1-bfhi(ah[0]));
                al[1]=pkbf(e2-bflo(ah[1]),e3-bfhi(ah[1]));
                al[2]=pkbf(f0-bflo(ah[2]),f1-bfhi(ah[2]));
                al[3]=pkbf(f2-bflo(ah[3]),f3-bfhi(ah[3]));
#pragma unroll
                for(int ntp2=0;ntp2<4;++ntp2){
                    uint32_t bh[4],bl[4];
                    ldsm4(fraddr(sb+AVH,ntp2*16,jh*64+kc2*16,272,lane),bh);
                    ldsm4(fraddr(sb+AVL,ntp2*16,jh*64+kc2*16,272,lane),bl);
                    mma16816(oacc[2*ntp2],  ah,bh[0],bh[2]);
                    mma16816(oacc[2*ntp2+1],ah,bh[1],bh[3]);
                    mma16816(oacc[2*ntp2],  ah,bl[0],bl[2]);
                    mma16816(oacc[2*ntp2+1],ah,bl[1],bl[3]);
                    mma16816(oacc[2*ntp2],  al,bh[0],bh[2]);
                    mma16816(oacc[2*ntp2+1],al,bh[1],bh[3]);
                }
            }
        }
    }

    // normalize + store fout + CTA-local gram/sums (k_gramf folded in)
    sum0+=__shfl_xor_sync(0xffffffffu,sum0,1);
    sum0+=__shfl_xor_sync(0xffffffffu,sum0,2);
    sum1+=__shfl_xor_sync(0xffffffffu,sum1,1);
    sum1+=__shfl_xor_sync(0xffffffffu,sum1,2);
    float inv0=1.f/sum0, inv1=1.f/sum1;
    int tig=lane&3;
    int r_lo=i0+g, r_hi=r_lo+8;
    float* Fs=(float*)sm_;   // [128 rows n][68 c] (Q region dead)
    __syncthreads();
#pragma unroll
    for(int nt=0;nt<8;++nt){
        int c0=nt*8+tig*2;
        float v0=oacc[nt][0]*inv0, v1=oacc[nt][1]*inv0;
        float v2=oacc[nt][2]*inv1, v3=oacc[nt][3]*inv1;
        Fs[r_lo*68+c0]=v0; Fs[r_lo*68+c0+1]=v1;
        Fs[r_hi*68+c0]=v2; Fs[r_hi*68+c0+1]=v3;
        g_fout[((size_t)(b*64)+c0  )*N_+q0+r_lo]=v0;
        g_fout[((size_t)(b*64)+c0+1)*N_+q0+r_lo]=v1;
        g_fout[((size_t)(b*64)+c0  )*N_+q0+r_hi]=v2;
        g_fout[((size_t)(b*64)+c0+1)*N_+q0+r_hi]=v3;
    }
    __syncthreads();
    {
        int ty=tid>>4, tx=tid&15;
        float acc[4][4];
#pragma unroll
        for(int r=0;r<4;++r){acc[r][0]=acc[r][1]=acc[r][2]=acc[r][3]=0.f;}
        for(int d=0;d<128;++d){
            float a0=Fs[d*68+4*ty+0],a1=Fs[d*68+4*ty+1],a2=Fs[d*68+4*ty+2],a3=Fs[d*68+4*ty+3];
            float b0=Fs[d*68+4*tx+0],b1=Fs[d*68+4*tx+1],b2=Fs[d*68+4*tx+2],b3=Fs[d*68+4*tx+3];
            acc[0][0]+=a0*b0;acc[0][1]+=a0*b1;acc[0][2]+=a0*b2;acc[0][3]+=a0*b3;
            acc[1][0]+=a1*b0;acc[1][1]+=a1*b1;acc[1][2]+=a1*b2;acc[1][3]+=a1*b3;
            acc[2][0]+=a2*b0;acc[2][1]+=a2*b1;acc[2][2]+=a2*b2;acc[2][3]+=a2*b3;
            acc[3][0]+=a3*b0;acc[3][1]+=a3*b1;acc[3][2]+=a3*b2;acc[3][3]+=a3*b3;
        }
#pragma unroll
        for(int r=0;r<4;++r)
#pragma unroll
            for(int c=0;c<4;++c)
                atomicAdd(&g_gramf[(4*ty+r)*64+4*tx+c],acc[r][c]);
        if(tid<64){
            float rs=0.f;
            for(int d=0;d<128;++d)rs+=Fs[d*68+tid];
            atomicAdd(&g_sumf[tid],rs);
        }
    }
}

__global__ void k_bnup(const float* __restrict__ wu, const float* __restrict__ gu,
                       const float* __restrict__ bu)
{
    __shared__ float s1[64], s2[64];
    int c=blockIdx.x, t=threadIdx.x;
    float tmp=0.f;
#pragma unroll 8
    for(int k=0;k<64;++k)tmp+=g_gramf[t*64+k]*wu[c*64+k];
    float wt=wu[c*64+t];
    s1[t]=wt*tmp; s2[t]=wt*g_sumf[t];
    __syncthreads();
    for(int off=32;off;off>>=1){
        if(t<off){s1[t]+=s1[t+off];s2[t]+=s2[t+off];}
        __syncthreads();
    }
    if(t==0){
        float mean=s2[0]*INVT_;
        float var=s1[0]*INVT_-mean*mean;
        float a=gu[c]*rsqrtf(var+EPS_);
        g_au[c]=a; g_bu[c]=bu[c]-a*mean;
    }
}

__global__ __launch_bounds__(256) void k_final(const float* __restrict__ x,
                                               const float* __restrict__ wu,
                                               float* __restrict__ out)
{
    __shared__ __align__(16) float Ws[16*68];
    __shared__ __align__(16) float Xs[16*132];
    int n0=blockIdx.x*128, c0=blockIdx.y*64, b=blockIdx.z;
    const float* F=g_fout+(size_t)b*M_*N_;
    int tid=threadIdx.x, ty=tid>>5, tx=tid&31;
    if(blockIdx.x==0&&blockIdx.y==0&&blockIdx.z==0){
        for(int i=tid;i<4096;i+=256)g_gramf[i]=0.f;
        if(tid<64)g_sumf[tid]=0.f;
    }
    u64 acc[4][4];
#pragma unroll
    for(int r=0;r<4;++r){acc[r][0]=acc[r][1]=acc[r][2]=acc[r][3]=0ull;}
    for(int k0=0;k0<64;k0+=16){
        {int m=tid>>2,kq=tid&3;
         float4 w4=*(const float4*)(wu+(size_t)(c0+m)*64+k0+4*kq);
         Ws[(4*kq+0)*68+m]=w4.x;Ws[(4*kq+1)*68+m]=w4.y;Ws[(4*kq+2)*68+m]=w4.z;Ws[(4*kq+3)*68+m]=w4.w;}
#pragma unroll
        for(int it=0;it<2;++it){int idx=it*256+tid,k=idx>>5,nq=idx&31;
            *(float4*)(Xs+k*132+4*nq)=*(const float4*)(F+(size_t)(k0+k)*N_+n0+4*nq);}
        __syncthreads();
#pragma unroll
        for(int d=0;d<16;++d){
            ulonglong2 a01=*(const ulonglong2*)(Ws+d*68+8*ty);
            ulonglong2 a23=*(const ulonglong2*)(Ws+d*68+8*ty+4);
            float4 bb=*(const float4*)(Xs+d*132+4*tx);
            u64 b0=d2(bb.x),b1=d2(bb.y),b2=d2(bb.z),b3=d2(bb.w);
            u64 av[4]={a01.x,a01.y,a23.x,a23.y};
#pragma unroll
            for(int r=0;r<4;++r){fma2(acc[r][0],av[r],b0);fma2(acc[r][1],av[r],b1);fma2(acc[r][2],av[r],b2);fma2(acc[r][3],av[r],b3);}
        }
        __syncthreads();
    }
#pragma unroll
    for(int r=0;r<4;++r){
        float l0,h0,l1,h1,l2,h2,l3,h3;
        up2(acc[r][0],l0,h0);up2(acc[r][1],l1,h1);up2(acc[r][2],l2,h2);up2(acc[r][3],l3,h3);
        int cl=c0+8*ty+2*r, ch=cl+1;
        float al=g_au[cl],bl=g_bu[cl],ah=g_au[ch],bh=g_bu[ch];
        size_t ol=((size_t)b*CX+cl)*N_+n0+4*tx;
        size_t oh=((size_t)b*CX+ch)*N_+n0+4*tx;
        float4 xl=*(const float4*)(x+ol);
        float4 xh=*(const float4*)(x+oh);
        *(float4*)(out+ol)=make_float4(xl.x+al*l0+bl,xl.y+al*l1+bl,xl.z+al*l2+bl,xl.w+al*l3+bl);
        *(float4*)(out+oh)=make_float4(xh.x+ah*h0+bh,xh.y+ah*h1+bh,xh.z+ah*h2+bh,xh.w+ah*h3+bh);
    }
}

extern "C" void kernel_launch(void* const* d_in, const int* in_sizes, int n_in,
                              void* d_out, int out_size)
{
    const float* x   = (const float*)d_in[0];
    const float* y   = (const float*)d_in[1];
    const float* ws1 = (const float*)d_in[2];
    const float* gs1 = (const float*)d_in[3];
    const float* ws2 = (const float*)d_in[5];
    const float* gs2 = (const float*)d_in[6];
    const float* bs2 = (const float*)d_in[7];
    const float* wx1 = (const float*)d_in[8];
    const float* gx1 = (const float*)d_in[9];
    const float* wx2 = (const float*)d_in[11];
    const float* gx2 = (const float*)d_in[12];
    const float* bx2 = (const float*)d_in[13];
    const float* wy1 = (const float*)d_in[14];
    const float* gy1 = (const float*)d_in[15];
    const float* wy2 = (const float*)d_in[17];
    const float* gy2 = (const float*)d_in[18];
    const float* by2 = (const float*)d_in[19];
    const float* wu  = (const float*)d_in[20];
    const float* gu  = (const float*)d_in[21];
    const float* bu  = (const float*)d_in[22];
    float* out = (float*)d_out;

    cudaFuncSetAttribute(k_attn, cudaFuncAttributeMaxDynamicSharedMemorySize, ATTN_SMEM);

    k_splitx<<<dim3(32, 24, B_), 256>>>(x, y);
    k_gemm1h<<<dim3(32, B_, 3), 256>>>(ws1, wx1, wy1);
    k_prep1<<<96, 256>>>(ws2, wx2, wy2, gs1, gx1, gy1,
                         gs2, bs2, gx2, bx2, gy2, by2);
    k_gemm2<<<dim3(32, 12), 256>>>();
    k_attn<<<dim3(32, B_), 256, ATTN_SMEM>>>();
    k_bnup<<<512, 64>>>(wu, gu, bu);
    k_final<<<dim3(32, 8, B_), 256>>>(x, wu, out);
}